// round 1
// baseline (speedup 1.0000x reference)
#include <cuda_runtime.h>
#include <cstdint>

// HashGrid encode: 16 levels, F=2, T=2^19, base_res=16, per_level_scale=2.0,
// smoothstep interpolation, 2D inputs. Levels 0..5 dense, 6..15 hashed.

#define NLEVELS 16
#define LOG2_T 19
#define TSIZE (1u << LOG2_T)
#define PRIME1 2654435761u

__global__ __launch_bounds__(256) void hashgrid_encode_kernel(
    const float2* __restrict__ x,          // [N] points, 2 coords each, in [-1,1]
    const float2* __restrict__ table,      // [16 * T] float2 entries
    float* __restrict__ out,               // [N, 32]
    int n)
{
    int i = blockIdx.x * blockDim.x + threadIdx.x;
    if (i >= n) return;

    float2 xi = __ldg(&x[i]);
    // map [-1,1] -> [0,1]
    float x0 = xi.x * 0.5f + 0.5f;
    float x1 = xi.y * 0.5f + 0.5f;

    float acc[2 * NLEVELS];

#pragma unroll
    for (int l = 0; l < NLEVELS; ++l) {
        const unsigned res = 16u << l;                 // grid resolution (power of 2)
        const float scale = (float)(res - 1u);         // 2^l * 16 - 1

        float p0 = x0 * scale + 0.5f;
        float p1 = x1 * scale + 0.5f;
        float fl0 = floorf(p0);
        float fl1 = floorf(p1);
        float fr0 = p0 - fl0;
        float fr1 = p1 - fl1;
        unsigned g0 = (unsigned)(int)fl0;
        unsigned g1 = (unsigned)(int)fl1;

        // smoothstep weights
        float w0 = fr0 * fr0 * (3.0f - 2.0f * fr0);
        float w1 = fr1 * fr1 * (3.0f - 2.0f * fr1);

        unsigned cx0 = g0, cx1 = g0 + 1u;
        unsigned cy0 = g1, cy1 = g1 + 1u;

        unsigned i00, i10, i01, i11;
        if (l <= 5) {
            // dense level: idx = (cx + cy*res) mod res^2; res^2 is a power of two
            const unsigned mask = (res * res) - 1u;
            i00 = (cx0 + cy0 * res) & mask;
            i10 = (cx1 + cy0 * res) & mask;
            i01 = (cx0 + cy1 * res) & mask;
            i11 = (cx1 + cy1 * res) & mask;
        } else {
            // hashed level: (x*1) ^ (y*prime1), masked to T
            const unsigned hmask = TSIZE - 1u;
            unsigned hy0 = cy0 * PRIME1;
            unsigned hy1 = cy1 * PRIME1;
            i00 = (cx0 ^ hy0) & hmask;
            i10 = (cx1 ^ hy0) & hmask;
            i01 = (cx0 ^ hy1) & hmask;
            i11 = (cx1 ^ hy1) & hmask;
        }

        const float2* tl = table + (size_t)l * TSIZE;
        float2 f00 = __ldg(tl + i00);
        float2 f10 = __ldg(tl + i10);
        float2 f01 = __ldg(tl + i01);
        float2 f11 = __ldg(tl + i11);

        float c00 = (1.0f - w0) * (1.0f - w1);
        float c10 = w0 * (1.0f - w1);
        float c01 = (1.0f - w0) * w1;
        float c11 = w0 * w1;

        float sx = c00 * f00.x + c10 * f10.x + c01 * f01.x + c11 * f11.x;
        float sy = c00 * f00.y + c10 * f10.y + c01 * f01.y + c11 * f11.y;

        acc[2 * l]     = sx;
        acc[2 * l + 1] = sy;
    }

    // 128 contiguous bytes per thread, 8x STG.128
    float4* o4 = reinterpret_cast<float4*>(out + (size_t)i * (2 * NLEVELS));
#pragma unroll
    for (int k = 0; k < (2 * NLEVELS) / 4; ++k) {
        o4[k] = make_float4(acc[4 * k], acc[4 * k + 1], acc[4 * k + 2], acc[4 * k + 3]);
    }
}

extern "C" void kernel_launch(void* const* d_in, const int* in_sizes, int n_in,
                              void* d_out, int out_size)
{
    const float2* x     = (const float2*)d_in[0];   // [N,2] float32
    const float2* table = (const float2*)d_in[1];   // [16, T, 2] float32
    float* out          = (float*)d_out;            // [N, 32] float32

    int n = in_sizes[0] / 2;  // number of points
    int threads = 256;
    int blocks = (n + threads - 1) / threads;
    hashgrid_encode_kernel<<<blocks, threads>>>(x, table, out, n);
}